// round 1
// baseline (speedup 1.0000x reference)
#include <cuda_runtime.h>
#include <math.h>

#define B 8
#define L 2048
#define D 64
#define BL (B*L)                     // 16384 rows per tensor
#define NROWS (2*BL)                 // 32768 rows (q then k)
#define ATTN_ELEMS ((long)BL * L)    // 33,554,432

// ---------------- scratch (device globals; no allocation allowed) ----------------
__device__ float g_qnT[B * D * L];   // [b][d][q]  4 MB
__device__ float g_knT[B * D * L];   // [b][d][k]  4 MB
__device__ float g_logZ[BL];         // per (b,q) row

// ---------------- K1: L2-normalize rows of q and k, store transposed ----------------
// One block = 32 rows of 64. Rows 0..BL-1 are q, BL..2BL-1 are k.
__global__ void k_norm_t(const float* __restrict__ q, const float* __restrict__ k) {
    __shared__ float tile[32][65];
    __shared__ float inv[32];
    const int t = threadIdx.x;
    const long gr0 = (long)blockIdx.x * 32;

    const float* src;
    float* dst;
    long base;
    if (gr0 < BL) { src = q; dst = g_qnT; base = gr0; }
    else          { src = k; dst = g_knT; base = gr0 - BL; }

    // load 32 rows x 64 cols, coalesced
#pragma unroll
    for (int i = 0; i < 8; i++) {
        int f = t + 256 * i;          // 0..2047
        int r = f >> 6, d = f & 63;
        tile[r][d] = src[(base + r) * 64 + d];
    }
    __syncthreads();

    if (t < 32) {
        float ss = 0.0f;
#pragma unroll
        for (int d = 0; d < 64; d++) { float x = tile[t][d]; ss += x * x; }
        float n = sqrtf(ss);
        inv[t] = 1.0f / fmaxf(n, 1e-12f);
    }
    __syncthreads();

    const int b  = (int)(base >> 11);     // /2048
    const int l0 = (int)(base & 2047);
#pragma unroll
    for (int i = 0; i < 8; i++) {
        int f = t + 256 * i;          // 0..2047
        int d = f >> 5, c = f & 31;
        dst[((long)b * 64 + d) * 2048 + l0 + c] = tile[c][d] * inv[c];
    }
}

// ---------------- K2: s = qn @ kn^T * (1/25) -> attn region (as scratch) ----------------
// CTA tile: 128 (q) x 64 (k), K=64. 256 threads, 8x4 micro-tile. smem = 48KB exactly.
__global__ void k_scores(float* __restrict__ s_out) {
    __shared__ float As[64][128];   // [d][q]
    __shared__ float Bs[64][64];    // [d][k]
    const int t = threadIdx.x;
    const int ktile = blockIdx.x;   // 0..31
    const int qtile = blockIdx.y;   // 0..15
    const int b = blockIdx.z;

    const float* aT = g_qnT + (long)b * 64 * 2048 + qtile * 128;
    const float* bT = g_knT + (long)b * 64 * 2048 + ktile * 64;

#pragma unroll
    for (int i = 0; i < 8; i++) {               // As: 64x128 = 2048 float4
        int f = t + 256 * i;
        int d = f >> 5, qv = f & 31;
        *(float4*)&As[d][qv * 4] = *(const float4*)&aT[(long)d * 2048 + qv * 4];
    }
#pragma unroll
    for (int i = 0; i < 4; i++) {               // Bs: 64x64 = 1024 float4
        int f = t + 256 * i;
        int d = f >> 4, kv = f & 15;
        *(float4*)&Bs[d][kv * 4] = *(const float4*)&bT[(long)d * 2048 + kv * 4];
    }
    __syncthreads();

    const int tq = t >> 4;   // 0..15 -> 8 q rows each
    const int tk = t & 15;   // 0..15 -> 4 k cols each
    float acc[8][4];
#pragma unroll
    for (int i = 0; i < 8; i++)
#pragma unroll
        for (int j = 0; j < 4; j++) acc[i][j] = 0.0f;

#pragma unroll
    for (int kk = 0; kk < 64; kk++) {
        float a[8];
        float4 a0 = *(float4*)&As[kk][tq * 8];
        float4 a1 = *(float4*)&As[kk][tq * 8 + 4];
        a[0]=a0.x; a[1]=a0.y; a[2]=a0.z; a[3]=a0.w;
        a[4]=a1.x; a[5]=a1.y; a[6]=a1.z; a[7]=a1.w;
        float4 bv = *(float4*)&Bs[kk][tk * 4];
#pragma unroll
        for (int i = 0; i < 8; i++) {
            acc[i][0] += a[i] * bv.x;
            acc[i][1] += a[i] * bv.y;
            acc[i][2] += a[i] * bv.z;
            acc[i][3] += a[i] * bv.w;
        }
    }

    const float scale = 1.0f / 25.0f;
    float* srow = s_out + ((long)b * L + qtile * 128) * L + ktile * 64;
#pragma unroll
    for (int i = 0; i < 8; i++) {
        float4 w;
        w.x = acc[i][0] * scale; w.y = acc[i][1] * scale;
        w.z = acc[i][2] * scale; w.w = acc[i][3] * scale;
        *(float4*)&srow[(long)(tq * 8 + i) * L + tk * 4] = w;
    }
}

// ---------------- K3: logZ per row. Scores are tiny (|s|<=0.04) so no max needed. ----------------
__global__ void k_rowsum(const float* __restrict__ s) {
    const int w = threadIdx.x >> 5, lane = threadIdx.x & 31;
    const long row = (long)blockIdx.x * 8 + w;
    const float* r = s + row * L;
    float z = 0.0f;
#pragma unroll
    for (int i = 0; i < 16; i++) {
        float4 v = *(const float4*)&r[i * 128 + lane * 4];
        z += __expf(v.x) + __expf(v.y) + __expf(v.z) + __expf(v.w);
    }
#pragma unroll
    for (int o = 16; o; o >>= 1) z += __shfl_xor_sync(0xFFFFFFFFu, z, o);
    if (lane == 0) g_logZ[row] = logf(z);
}

// ---------------- K4: in-place softmax: attn = exp(s - logZ), log_attn = s - logZ ----------------
__global__ void k_softmax(float* __restrict__ attn, float* __restrict__ log_attn) {
    const long idx4 = (long)blockIdx.x * 256 + threadIdx.x;
    const long idx = idx4 * 4;
    const long row = idx >> 11;            // /2048, all 4 elems same row
    const float lz = g_logZ[row];
    float4 sv = *(float4*)&attn[idx];      // raw scores (scratch)
    float4 la, a;
    la.x = sv.x - lz; la.y = sv.y - lz; la.z = sv.z - lz; la.w = sv.w - lz;
    a.x = __expf(la.x); a.y = __expf(la.y); a.z = __expf(la.z); a.w = __expf(la.w);
    *(float4*)&attn[idx] = a;
    *(float4*)&log_attn[idx] = la;
}

// ---------------- K5: out = attn @ v. CTA tile 32(q) x 64(d), K-loop 64. 128 threads. ----------------
__global__ void k_av(const float* __restrict__ attn, const float* __restrict__ v,
                     float* __restrict__ out) {
    __shared__ float As[32][66];   // attn tile, padded
    __shared__ float Vs[64][64];   // v tile
    const int t = threadIdx.x;     // 128
    const int qtile = blockIdx.x;  // 0..63
    const int b = blockIdx.y;

    const float* arow = attn + ((long)b * L + qtile * 32) * L;
    const float* vb = v + (long)b * L * 64;

    const int qg = t >> 4;   // 0..7  -> 4 q rows each
    const int dg = t & 15;   // 0..15 -> 4 d cols each
    float acc[4][4];
#pragma unroll
    for (int i = 0; i < 4; i++)
#pragma unroll
        for (int j = 0; j < 4; j++) acc[i][j] = 0.0f;

    for (int kc = 0; kc < 32; kc++) {
#pragma unroll
        for (int i = 0; i < 4; i++) {            // As: 32x64 = 512 float4
            int f = t + 128 * i;
            int r = f >> 4, c4 = f & 15;
            float4 x = *(const float4*)&arow[(long)r * L + kc * 64 + c4 * 4];
            As[r][c4 * 4 + 0] = x.x; As[r][c4 * 4 + 1] = x.y;
            As[r][c4 * 4 + 2] = x.z; As[r][c4 * 4 + 3] = x.w;
        }
#pragma unroll
        for (int i = 0; i < 8; i++) {            // Vs: 64x64 = 1024 float4
            int f = t + 128 * i;
            int r = f >> 4, c4 = f & 15;
            *(float4*)&Vs[r][c4 * 4] = *(const float4*)&vb[(long)(kc * 64 + r) * 64 + c4 * 4];
        }
        __syncthreads();

#pragma unroll
        for (int kk = 0; kk < 64; kk++) {
            float a0 = As[qg * 4 + 0][kk];
            float a1 = As[qg * 4 + 1][kk];
            float a2 = As[qg * 4 + 2][kk];
            float a3 = As[qg * 4 + 3][kk];
            float4 vv = *(float4*)&Vs[kk][dg * 4];
            acc[0][0] += a0 * vv.x; acc[0][1] += a0 * vv.y; acc[0][2] += a0 * vv.z; acc[0][3] += a0 * vv.w;
            acc[1][0] += a1 * vv.x; acc[1][1] += a1 * vv.y; acc[1][2] += a1 * vv.z; acc[1][3] += a1 * vv.w;
            acc[2][0] += a2 * vv.x; acc[2][1] += a2 * vv.y; acc[2][2] += a2 * vv.z; acc[2][3] += a2 * vv.w;
            acc[3][0] += a3 * vv.x; acc[3][1] += a3 * vv.y; acc[3][2] += a3 * vv.z; acc[3][3] += a3 * vv.w;
        }
        __syncthreads();
    }

    float* orow = out + ((long)b * L + qtile * 32) * 64;
#pragma unroll
    for (int i = 0; i < 4; i++) {
        float4 w;
        w.x = acc[i][0]; w.y = acc[i][1]; w.z = acc[i][2]; w.w = acc[i][3];
        *(float4*)&orow[(long)(qg * 4 + i) * 64 + dg * 4] = w;
    }
}

// ---------------- launcher ----------------
extern "C" void kernel_launch(void* const* d_in, const int* in_sizes, int n_in,
                              void* d_out, int out_size) {
    const float* q = (const float*)d_in[0];
    const float* k = (const float*)d_in[1];
    const float* v = (const float*)d_in[2];

    float* out   = (float*)d_out;
    float* out_o = out;                          // [B,L,64]
    float* attn  = out + (long)BL * 64;          // [B,L,L]
    float* lattn = attn + ATTN_ELEMS;            // [B,L,L]

    k_norm_t<<<NROWS / 32, 256>>>(q, k);

    dim3 g2(L / 64, L / 128, B);                 // (32,16,8)
    k_scores<<<g2, 256>>>(attn);

    k_rowsum<<<BL / 8, 256>>>(attn);

    k_softmax<<<(unsigned)(ATTN_ELEMS / 1024), 256>>>(attn, lattn);

    dim3 g5(L / 32, B);                          // (64,8)
    k_av<<<g5, 128>>>(attn, v, out_o);
}

// round 3
// speedup vs baseline: 2.2129x; 2.2129x over previous
#include <cuda_runtime.h>
#include <cuda_bf16.h>
#include <math.h>
#include <stdint.h>

#define B 8
#define L 2048
#define D 64
#define BL (B*L)

// ---------------- device scratch (no allocations allowed) ----------------
__device__ __nv_bfloat16 g_qn[BL * D];   // normalized q, bf16, [b][l][d]
__device__ __nv_bfloat16 g_kn[BL * D];   // normalized k, bf16
__device__ __nv_bfloat16 g_vb[BL * D];   // v in bf16
__device__ float g_vsum[B * D];          // per-batch column sums of v (fp32)
__device__ float g_Z[BL];                // sum exp(s) per row
__device__ float g_logZ[BL];
__device__ float g_invZ[BL];

// ---------------- PTX helpers ----------------
static __device__ __forceinline__ uint32_t smem_u32(const void* p) {
    return (uint32_t)__cvta_generic_to_shared(p);
}
static __device__ __forceinline__ void ldmat_x4(uint32_t& r0, uint32_t& r1, uint32_t& r2, uint32_t& r3, uint32_t addr) {
    asm volatile("ldmatrix.sync.aligned.m8n8.x4.shared.b16 {%0,%1,%2,%3}, [%4];"
                 : "=r"(r0), "=r"(r1), "=r"(r2), "=r"(r3) : "r"(addr));
}
static __device__ __forceinline__ void ldmat_x4_t(uint32_t& r0, uint32_t& r1, uint32_t& r2, uint32_t& r3, uint32_t addr) {
    asm volatile("ldmatrix.sync.aligned.m8n8.x4.trans.shared.b16 {%0,%1,%2,%3}, [%4];"
                 : "=r"(r0), "=r"(r1), "=r"(r2), "=r"(r3) : "r"(addr));
}
static __device__ __forceinline__ void mma_bf16(float& c0, float& c1, float& c2, float& c3,
    uint32_t a0, uint32_t a1, uint32_t a2, uint32_t a3, uint32_t b0, uint32_t b1) {
    asm volatile("mma.sync.aligned.m16n8k16.row.col.f32.bf16.bf16.f32 "
                 "{%0,%1,%2,%3}, {%4,%5,%6,%7}, {%8,%9}, {%0,%1,%2,%3};"
                 : "+f"(c0), "+f"(c1), "+f"(c2), "+f"(c3)
                 : "r"(a0), "r"(a1), "r"(a2), "r"(a3), "r"(b0), "r"(b1));
}
static __device__ __forceinline__ uint32_t pack2(float lo, float hi) {
    __nv_bfloat162 h = __floats2bfloat162_rn(lo, hi);
    return *reinterpret_cast<uint32_t*>(&h);
}

// ---------------- K0: zero the atomic accumulators ----------------
__global__ void k_zero() {
    int i = blockIdx.x * 256 + threadIdx.x;
    if (i < BL) g_Z[i] = 0.0f;
    if (i < B * D) g_vsum[i] = 0.0f;
}

// ---------------- K1a: l2-normalize q,k -> bf16 (one warp per row) ----------------
__global__ void k_prep_qk(const float* __restrict__ q, const float* __restrict__ k) {
    const int w = threadIdx.x >> 5, lane = threadIdx.x & 31;
    const long row = (long)blockIdx.x * 8 + w;
    const float* src;
    __nv_bfloat16* dst;
    long r;
    if (row < BL) { src = q; dst = g_qn; r = row; }
    else          { src = k; dst = g_kn; r = row - BL; }
    float2 x = *(const float2*)&src[r * 64 + lane * 2];
    float ss = x.x * x.x + x.y * x.y;
#pragma unroll
    for (int o = 16; o; o >>= 1) ss += __shfl_xor_sync(0xFFFFFFFFu, ss, o);
    float inv = 1.0f / fmaxf(sqrtf(ss), 1e-12f);
    __nv_bfloat162 h = __floats2bfloat162_rn(x.x * inv, x.y * inv);
    *(__nv_bfloat162*)&dst[r * 64 + lane * 2] = h;
}

// ---------------- K1b: v -> bf16 and per-batch column sums ----------------
__global__ void k_prep_v(const float* __restrict__ v) {
    __shared__ float red[4][64];
    const int t = threadIdx.x;
    const int d = t & 63, g = t >> 6;            // column, row-group
    const long base = (long)blockIdx.x * 64;     // 64 rows per block
    const int b = (int)(base >> 11);
    float s = 0.0f;
#pragma unroll
    for (int i = 0; i < 16; i++) {
        long r = base + g + 4 * i;
        float x = v[r * 64 + d];
        s += x;
        g_vb[r * 64 + d] = __float2bfloat16_rn(x);
    }
    red[g][d] = s;
    __syncthreads();
    if (t < 64) {
        float tot = red[0][t] + red[1][t] + red[2][t] + red[3][t];
        atomicAdd(&g_vsum[b * 64 + t], tot);
    }
}

// ---------------- K2: s = q̂k̂ᵀ/25 via bf16 mma; write s; accumulate Z ----------------
// CTA tile 128q x 128k, 8 warps, each warp 16 rows x 128 cols.
__global__ void __launch_bounds__(256) k_scores(float* __restrict__ s_out) {
    __shared__ __align__(16) __nv_bfloat16 qs[128][72];
    __shared__ __align__(16) __nv_bfloat16 ks_s[128][72];
    const int t = threadIdx.x, w = t >> 5, lane = t & 31;
    const int kt = blockIdx.x, qt = blockIdx.y, b = blockIdx.z;

    const __nv_bfloat16* qg = g_qn + ((long)b * L + qt * 128) * 64;
    const __nv_bfloat16* kg = g_kn + ((long)b * L + kt * 128) * 64;
#pragma unroll
    for (int i = 0; i < 4; i++) {
        int f = t + 256 * i;           // 0..1023
        int r = f >> 3, c = f & 7;
        *(uint4*)&qs[r][c * 8]   = *(const uint4*)&qg[r * 64 + c * 8];
        *(uint4*)&ks_s[r][c * 8] = *(const uint4*)&kg[r * 64 + c * 8];
    }
    __syncthreads();

    const int m0 = w * 16;
    // A fragments for the 4 k-steps (d dimension, 64/16)
    uint32_t A[4][4];
#pragma unroll
    for (int ksi = 0; ksi < 4; ksi++) {
        uint32_t addr = smem_u32(&qs[m0 + (lane & 15)][ksi * 16 + ((lane >> 4) << 3)]);
        ldmat_x4(A[ksi][0], A[ksi][1], A[ksi][2], A[ksi][3], addr);
    }

    const int r = lane >> 2, c2 = (lane & 3) * 2;
    const long grow = (long)b * L + qt * 128 + m0 + r;
    float* sA = s_out + grow * L + kt * 128;
    float* sB = sA + (long)8 * L;
    const float scale = 1.0f / 25.0f;
    float zA = 0.0f, zB = 0.0f;

#pragma unroll
    for (int nt2 = 0; nt2 < 8; nt2++) {
        float c[2][4] = {{0.f,0.f,0.f,0.f},{0.f,0.f,0.f,0.f}};
#pragma unroll
        for (int ksi = 0; ksi < 4; ksi++) {
            uint32_t b0, b1, b2, b3;
            uint32_t addr = smem_u32(&ks_s[nt2 * 16 + ((lane >> 4) << 3) + (lane & 7)]
                                          [ksi * 16 + (((lane >> 3) & 1) << 3)]);
            ldmat_x4(b0, b1, b2, b3, addr);
            mma_bf16(c[0][0], c[0][1], c[0][2], c[0][3], A[ksi][0], A[ksi][1], A[ksi][2], A[ksi][3], b0, b1);
            mma_bf16(c[1][0], c[1][1], c[1][2], c[1][3], A[ksi][0], A[ksi][1], A[ksi][2], A[ksi][3], b2, b3);
        }
#pragma unroll
        for (int j = 0; j < 2; j++) {
            int nt = 2 * nt2 + j;
            float s0 = c[j][0] * scale, s1 = c[j][1] * scale;
            float s2 = c[j][2] * scale, s3 = c[j][3] * scale;
            zA += __expf(s0) + __expf(s1);
            zB += __expf(s2) + __expf(s3);
            *(float2*)&sA[nt * 8 + c2] = make_float2(s0, s1);
            *(float2*)&sB[nt * 8 + c2] = make_float2(s2, s3);
        }
    }
    zA += __shfl_xor_sync(0xFFFFFFFFu, zA, 1); zA += __shfl_xor_sync(0xFFFFFFFFu, zA, 2);
    zB += __shfl_xor_sync(0xFFFFFFFFu, zB, 1); zB += __shfl_xor_sync(0xFFFFFFFFu, zB, 2);
    if ((lane & 3) == 0) {
        atomicAdd(&g_Z[grow], zA);
        atomicAdd(&g_Z[grow + 8], zB);
    }
}

// ---------------- K2b: logZ / invZ ----------------
__global__ void k_logz() {
    int i = blockIdx.x * 256 + threadIdx.x;
    float z = g_Z[i];
    g_logZ[i] = logf(z);
    g_invZ[i] = 1.0f / z;
}

// ---------------- K3: fused softmax outputs + AV GEMM ----------------
// CTA = 128 q rows x full K loop. Reads s (in attn region), writes attn + log_attn,
// accumulates out = (vsum + (e^s-1) @ v) / Z via bf16 mma (C-fragment -> A-fragment reuse).
__global__ void __launch_bounds__(256) k_fused(float* attn, float* __restrict__ lattn,
                                               float* __restrict__ out) {
    __shared__ __align__(16) __nv_bfloat16 vs[128][72];
    const int t = threadIdx.x, w = t >> 5, lane = t & 31;
    const int qt = blockIdx.x, b = blockIdx.y;
    const int r = lane >> 2, c2 = (lane & 3) * 2;

    const long rowA = (long)b * L + qt * 128 + w * 16 + r;
    const float lzA = g_logZ[rowA], lzB = g_logZ[rowA + 8];
    const float izA = g_invZ[rowA], izB = g_invZ[rowA + 8];

    float vsum[16];
#pragma unroll
    for (int nt = 0; nt < 8; nt++) {
        vsum[2 * nt]     = g_vsum[b * 64 + nt * 8 + c2];
        vsum[2 * nt + 1] = g_vsum[b * 64 + nt * 8 + c2 + 1];
    }

    float* aA = attn + rowA * L;
    float* aB = aA + (long)8 * L;
    float* lA = lattn + rowA * L;
    float* lB = lA + (long)8 * L;
    const __nv_bfloat16* vgb = g_vb + (long)b * L * 64;

    float acc[8][4];
#pragma unroll
    for (int i = 0; i < 8; i++)
#pragma unroll
        for (int j = 0; j < 4; j++) acc[i][j] = 0.0f;

    for (int kc = 0; kc < 16; kc++) {
        // issue v-chunk loads (smem) and prefetch all s for this chunk (max MLP)
        uint4 vtmp[4];
#pragma unroll
        for (int i = 0; i < 4; i++) {
            int f = t + 256 * i;
            int vr = f >> 3, c8 = f & 7;
            vtmp[i] = *(const uint4*)&vgb[(kc * 128 + vr) * 64 + c8 * 8];
        }
        float2 Sa0[8], Sb0[8], Sa1[8], Sb1[8];
#pragma unroll
        for (int ksi = 0; ksi < 8; ksi++) {
            int col0 = kc * 128 + ksi * 16 + c2;
            Sa0[ksi] = *(float2*)&aA[col0];
            Sb0[ksi] = *(float2*)&aB[col0];
            Sa1[ksi] = *(float2*)&aA[col0 + 8];
            Sb1[ksi] = *(float2*)&aB[col0 + 8];
        }
        __syncthreads();     // previous chunk's ldmatrix done
#pragma unroll
        for (int i = 0; i < 4; i++) {
            int f = t + 256 * i;
            int vr = f >> 3, c8 = f & 7;
            *(uint4*)&vs[vr][c8 * 8] = vtmp[i];
        }
        __syncthreads();     // v chunk visible

#pragma unroll
        for (int ksi = 0; ksi < 8; ksi++) {
            int col0 = kc * 128 + ksi * 16 + c2;
            float ea0x = __expf(Sa0[ksi].x), ea0y = __expf(Sa0[ksi].y);
            float eb0x = __expf(Sb0[ksi].x), eb0y = __expf(Sb0[ksi].y);
            float ea1x = __expf(Sa1[ksi].x), ea1y = __expf(Sa1[ksi].y);
            float eb1x = __expf(Sb1[ksi].x), eb1y = __expf(Sb1[ksi].y);
            *(float2*)&lA[col0]     = make_float2(Sa0[ksi].x - lzA, Sa0[ksi].y - lzA);
            *(float2*)&lB[col0]     = make_float2(Sb0[ksi].x - lzB, Sb0[ksi].y - lzB);
            *(float2*)&lA[col0 + 8] = make_float2(Sa1[ksi].x - lzA, Sa1[ksi].y - lzA);
            *(float2*)&lB[col0 + 8] = make_float2(Sb1[ksi].x - lzB, Sb1[ksi].y - lzB);
            *(float2*)&aA[col0]     = make_float2(ea0x * izA, ea0y * izA);
            *(float2*)&aB[col0]     = make_float2(eb0x * izB, eb0y * izB);
            *(float2*)&aA[col0 + 8] = make_float2(ea1x * izA, ea1y * izA);
            *(float2*)&aB[col0 + 8] = make_float2(eb1x * izB, eb1y * izB);
            // t = e^s - 1 fragments become mma A operands directly
            uint32_t a0 = pack2(ea0x - 1.0f, ea0y - 1.0f);
            uint32_t a1 = pack2(eb0x - 1.0f, eb0y - 1.0f);
            uint32_t a2 = pack2(ea1x - 1.0f, ea1y - 1.0f);
            uint32_t a3 = pack2(eb1x - 1.0f, eb1y - 1.0f);
#pragma unroll
            for (int nn2 = 0; nn2 < 4; nn2++) {
                uint32_t b0, b1, b2, b3;
                uint32_t addr = smem_u32(&vs[ksi * 16 + ((lane >> 3) & 1) * 8 + (lane & 7)]
                                             [nn2 * 16 + ((lane >> 4) << 3)]);
                ldmat_x4_t(b0, b1, b2, b3, addr);
                mma_bf16(acc[2 * nn2][0], acc[2 * nn2][1], acc[2 * nn2][2], acc[2 * nn2][3],
                         a0, a1, a2, a3, b0, b1);
                mma_bf16(acc[2 * nn2 + 1][0], acc[2 * nn2 + 1][1], acc[2 * nn2 + 1][2], acc[2 * nn2 + 1][3],
                         a0, a1, a2, a3, b2, b3);
            }
        }
        __syncthreads();     // protect vs before next chunk store
    }

    float* oA = out + rowA * 64;
    float* oB = oA + 8 * 64;
#pragma unroll
    for (int nt = 0; nt < 8; nt++) {
        *(float2*)&oA[nt * 8 + c2] = make_float2((vsum[2 * nt] + acc[nt][0]) * izA,
                                                 (vsum[2 * nt + 1] + acc[nt][1]) * izA);
        *(float2*)&oB[nt * 8 + c2] = make_float2((vsum[2 * nt] + acc[nt][2]) * izB,
                                                 (vsum[2 * nt + 1] + acc[nt][3]) * izB);
    }
}

// ---------------- launcher ----------------
extern "C" void kernel_launch(void* const* d_in, const int* in_sizes, int n_in,
                              void* d_out, int out_size) {
    const float* q = (const float*)d_in[0];
    const float* k = (const float*)d_in[1];
    const float* v = (const float*)d_in[2];

    float* out   = (float*)d_out;                 // [B,L,64]
    float* attn  = out + (long)BL * 64;           // [B,L,L] (also s scratch)
    float* lattn = attn + (long)BL * L;           // [B,L,L]

    k_zero<<<64, 256>>>();
    k_prep_qk<<<2 * BL / 8, 256>>>(q, k);
    k_prep_v<<<BL / 64, 256>>>(v);

    dim3 g2(L / 128, L / 128, B);                 // (16,16,8)
    k_scores<<<g2, 256>>>(attn);

    k_logz<<<BL / 256, 256>>>();

    dim3 g3(L / 128, B);                          // (16,8)
    k_fused<<<g3, 256>>>(attn, lattn, out);
}

// round 5
// speedup vs baseline: 3.3878x; 1.5309x over previous
#include <cuda_runtime.h>
#include <cuda_bf16.h>
#include <math.h>
#include <stdint.h>

#define B 8
#define L 2048
#define D 64
#define BL (B*L)

// ---------------- device scratch ----------------
__device__ __nv_bfloat16 g_qn[BL * D];
__device__ __nv_bfloat16 g_kn[BL * D];
__device__ __nv_bfloat16 g_vb[BL * D];
__device__ float g_vsum[B * D];

// ---------------- PTX helpers ----------------
static __device__ __forceinline__ uint32_t smem_u32(const void* p) {
    return (uint32_t)__cvta_generic_to_shared(p);
}
static __device__ __forceinline__ void ldmat_x4(uint32_t& r0, uint32_t& r1, uint32_t& r2, uint32_t& r3, uint32_t addr) {
    asm volatile("ldmatrix.sync.aligned.m8n8.x4.shared.b16 {%0,%1,%2,%3}, [%4];"
                 : "=r"(r0), "=r"(r1), "=r"(r2), "=r"(r3) : "r"(addr));
}
static __device__ __forceinline__ void ldmat_x4_t(uint32_t& r0, uint32_t& r1, uint32_t& r2, uint32_t& r3, uint32_t addr) {
    asm volatile("ldmatrix.sync.aligned.m8n8.x4.trans.shared.b16 {%0,%1,%2,%3}, [%4];"
                 : "=r"(r0), "=r"(r1), "=r"(r2), "=r"(r3) : "r"(addr));
}
static __device__ __forceinline__ void mma_bf16(float& c0, float& c1, float& c2, float& c3,
    uint32_t a0, uint32_t a1, uint32_t a2, uint32_t a3, uint32_t b0, uint32_t b1) {
    asm volatile("mma.sync.aligned.m16n8k16.row.col.f32.bf16.bf16.f32 "
                 "{%0,%1,%2,%3}, {%4,%5,%6,%7}, {%8,%9}, {%0,%1,%2,%3};"
                 : "+f"(c0), "+f"(c1), "+f"(c2), "+f"(c3)
                 : "r"(a0), "r"(a1), "r"(a2), "r"(a3), "r"(b0), "r"(b1));
}
static __device__ __forceinline__ uint32_t pack2(float lo, float hi) {
    __nv_bfloat162 h = __floats2bfloat162_rn(lo, hi);
    return *reinterpret_cast<uint32_t*>(&h);
}
// e^s - 1 for |s| <= 0.04: cubic Taylor, abs err <= 1.1e-7. FMA pipe only.
static __device__ __forceinline__ float expm1s(float s) {
    float u = fmaf(s, 0.166666667f, 0.5f);
    u = fmaf(s, u, 1.0f);
    return s * u;
}

// ---------------- K0: zero vsum accumulators ----------------
__global__ void k_zero() {
    int i = blockIdx.x * 256 + threadIdx.x;
    if (i < B * D) g_vsum[i] = 0.0f;
}

// ---------------- K1a: l2-normalize q,k -> bf16 (one warp per row) ----------------
__global__ void k_prep_qk(const float* __restrict__ q, const float* __restrict__ k) {
    const int w = threadIdx.x >> 5, lane = threadIdx.x & 31;
    const long row = (long)blockIdx.x * 8 + w;
    const float* src;
    __nv_bfloat16* dst;
    long r;
    if (row < BL) { src = q; dst = g_qn; r = row; }
    else          { src = k; dst = g_kn; r = row - BL; }
    float2 x = *(const float2*)&src[r * 64 + lane * 2];
    float ss = x.x * x.x + x.y * x.y;
#pragma unroll
    for (int o = 16; o; o >>= 1) ss += __shfl_xor_sync(0xFFFFFFFFu, ss, o);
    float inv = 1.0f / fmaxf(sqrtf(ss), 1e-12f);
    __nv_bfloat162 h = __floats2bfloat162_rn(x.x * inv, x.y * inv);
    *(__nv_bfloat162*)&dst[r * 64 + lane * 2] = h;
}

// ---------------- K1b: v -> bf16 and per-batch column sums ----------------
__global__ void k_prep_v(const float* __restrict__ v) {
    __shared__ float red[4][64];
    const int t = threadIdx.x;
    const int d = t & 63, g = t >> 6;
    const long base = (long)blockIdx.x * 64;
    const int b = (int)(base >> 11);
    float s = 0.0f;
#pragma unroll
    for (int i = 0; i < 16; i++) {
        long r = base + g + 4 * i;
        float x = v[r * 64 + d];
        s += x;
        g_vb[r * 64 + d] = __float2bfloat16_rn(x);
    }
    red[g][d] = s;
    __syncthreads();
    if (t < 64) {
        float tot = red[0][t] + red[1][t] + red[2][t] + red[3][t];
        atomicAdd(&g_vsum[b * 64 + t], tot);
    }
}

// ---------------- K2: mega-kernel ----------------
// CTA = 128 q rows of one batch. Loop1: QK mma -> Z per row (registers only).
// Loop2: recompute QK, write attn & log_attn, AV mma with t = e^s - 1.
// smem: region0 = q tile (prologue) then v chunks (loop2); region1 = k chunks.
__global__ void __launch_bounds__(256) k_main(float* __restrict__ attn,
                                              float* __restrict__ lattn,
                                              float* __restrict__ out) {
    __shared__ __align__(16) __nv_bfloat16 sm0[128][72];  // q tile, later v chunk
    __shared__ __align__(16) __nv_bfloat16 sm1[128][72];  // k chunk
    const int t = threadIdx.x, w = t >> 5, lane = t & 31;
    const int qt = blockIdx.x, b = blockIdx.y;
    const int r = lane >> 2, c2 = (lane & 3) * 2;
    const float scale = 0.04f;   // 1/25

    const __nv_bfloat16* qg = g_qn + ((long)b * L + qt * 128) * 64;
    const __nv_bfloat16* kg = g_kn + (long)b * L * 64;
    const __nv_bfloat16* vg = g_vb + (long)b * L * 64;

    // ---- prologue: q tile -> smem -> A fragments ----
#pragma unroll
    for (int i = 0; i < 4; i++) {
        int f = t + 256 * i;
        int row = f >> 3, c = f & 7;
        *(uint4*)&sm0[row][c * 8] = *(const uint4*)&qg[row * 64 + c * 8];
    }
    __syncthreads();
    uint32_t A[4][4];
#pragma unroll
    for (int ksi = 0; ksi < 4; ksi++) {
        uint32_t addr = smem_u32(&sm0[w * 16 + (lane & 15)][ksi * 16 + ((lane >> 4) << 3)]);
        ldmat_x4(A[ksi][0], A[ksi][1], A[ksi][2], A[ksi][3], addr);
    }

    // ---- loop 1: Z per row (no stores) ----
    float tsumA = 0.0f, tsumB = 0.0f;
    {
        uint4 ktmp[4];
#pragma unroll
        for (int i = 0; i < 4; i++) {
            int f = t + 256 * i;
            int row = f >> 3, c = f & 7;
            ktmp[i] = *(const uint4*)&kg[row * 64 + c * 8];
        }
        for (int kc = 0; kc < 16; kc++) {
            __syncthreads();
#pragma unroll
            for (int i = 0; i < 4; i++) {
                int f = t + 256 * i;
                int row = f >> 3, c = f & 7;
                *(uint4*)&sm1[row][c * 8] = ktmp[i];
            }
            __syncthreads();
            if (kc < 15) {
#pragma unroll
                for (int i = 0; i < 4; i++) {
                    int f = t + 256 * i;
                    int row = f >> 3, c = f & 7;
                    ktmp[i] = *(const uint4*)&kg[((kc + 1) * 128 + row) * 64 + c * 8];
                }
            }
#pragma unroll
            for (int nt2 = 0; nt2 < 8; nt2++) {
                float cf[2][4] = {{0.f,0.f,0.f,0.f},{0.f,0.f,0.f,0.f}};
#pragma unroll
                for (int ksi = 0; ksi < 4; ksi++) {
                    uint32_t b0, b1, b2, b3;
                    uint32_t addr = smem_u32(&sm1[nt2 * 16 + ((lane >> 4) << 3) + (lane & 7)]
                                                  [ksi * 16 + (((lane >> 3) & 1) << 3)]);
                    ldmat_x4(b0, b1, b2, b3, addr);
                    mma_bf16(cf[0][0], cf[0][1], cf[0][2], cf[0][3], A[ksi][0], A[ksi][1], A[ksi][2], A[ksi][3], b0, b1);
                    mma_bf16(cf[1][0], cf[1][1], cf[1][2], cf[1][3], A[ksi][0], A[ksi][1], A[ksi][2], A[ksi][3], b2, b3);
                }
#pragma unroll
                for (int j = 0; j < 2; j++) {
                    tsumA += expm1s(cf[j][0] * scale) + expm1s(cf[j][1] * scale);
                    tsumB += expm1s(cf[j][2] * scale) + expm1s(cf[j][3] * scale);
                }
            }
        }
    }
    tsumA += __shfl_xor_sync(0xFFFFFFFFu, tsumA, 1);
    tsumA += __shfl_xor_sync(0xFFFFFFFFu, tsumA, 2);
    tsumB += __shfl_xor_sync(0xFFFFFFFFu, tsumB, 1);
    tsumB += __shfl_xor_sync(0xFFFFFFFFu, tsumB, 2);
    const float zA = 2048.0f + tsumA, zB = 2048.0f + tsumB;
    const float lzA = logf(zA), lzB = logf(zB);
    const float izA = 1.0f / zA,  izB = 1.0f / zB;

    // ---- loop 2: recompute, write attn/lattn, AV mma ----
    const long rowA = (long)b * L + qt * 128 + w * 16 + r;
    float* aA = attn + rowA * L;
    float* aB = aA + (long)8 * L;
    float* lA = lattn + rowA * L;
    float* lB = lA + (long)8 * L;

    float acc[8][4];
#pragma unroll
    for (int i = 0; i < 8; i++)
#pragma unroll
        for (int j = 0; j < 4; j++) acc[i][j] = 0.0f;

    {
        uint4 ktmp[4], vtmp[4];
#pragma unroll
        for (int i = 0; i < 4; i++) {
            int f = t + 256 * i;
            int row = f >> 3, c = f & 7;
            ktmp[i] = *(const uint4*)&kg[row * 64 + c * 8];
            vtmp[i] = *(const uint4*)&vg[row * 64 + c * 8];
        }
        for (int kc = 0; kc < 16; kc++) {
            __syncthreads();
#pragma unroll
            for (int i = 0; i < 4; i++) {
                int f = t + 256 * i;
                int row = f >> 3, c = f & 7;
                *(uint4*)&sm1[row][c * 8] = ktmp[i];
                *(uint4*)&sm0[row][c * 8] = vtmp[i];
            }
            __syncthreads();
            if (kc < 15) {
#pragma unroll
                for (int i = 0; i < 4; i++) {
                    int f = t + 256 * i;
                    int row = f >> 3, c = f & 7;
                    ktmp[i] = *(const uint4*)&kg[((kc + 1) * 128 + row) * 64 + c * 8];
                    vtmp[i] = *(const uint4*)&vg[((kc + 1) * 128 + row) * 64 + c * 8];
                }
            }
#pragma unroll
            for (int nt2 = 0; nt2 < 8; nt2++) {
                float cf[2][4] = {{0.f,0.f,0.f,0.f},{0.f,0.f,0.f,0.f}};
#pragma unroll
                for (int ksi = 0; ksi < 4; ksi++) {
                    uint32_t b0, b1, b2, b3;
                    uint32_t addr = smem_u32(&sm1[nt2 * 16 + ((lane >> 4) << 3) + (lane & 7)]
                                                  [ksi * 16 + (((lane >> 3) & 1) << 3)]);
                    ldmat_x4(b0, b1, b2, b3, addr);
                    mma_bf16(cf[0][0], cf[0][1], cf[0][2], cf[0][3], A[ksi][0], A[ksi][1], A[ksi][2], A[ksi][3], b0, b1);
                    mma_bf16(cf[1][0], cf[1][1], cf[1][2], cf[1][3], A[ksi][0], A[ksi][1], A[ksi][2], A[ksi][3], b2, b3);
                }
                const int col0 = kc * 128 + nt2 * 16 + c2;
                float s00 = cf[0][0] * scale, s01 = cf[0][1] * scale;  // row r,   cols c2   (grp0)
                float s10 = cf[0][2] * scale, s11 = cf[0][3] * scale;  // row r+8, cols c2   (grp0)
                float s20 = cf[1][0] * scale, s21 = cf[1][1] * scale;  // row r,   cols c2+8 (grp1)
                float s30 = cf[1][2] * scale, s31 = cf[1][3] * scale;  // row r+8, cols c2+8 (grp1)
                float t00 = expm1s(s00), t01 = expm1s(s01);
                float t10 = expm1s(s10), t11 = expm1s(s11);
                float t20 = expm1s(s20), t21 = expm1s(s21);
                float t30 = expm1s(s30), t31 = expm1s(s31);
                // streaming stores (never re-read)
                __stcs((float2*)&lA[col0],     make_float2(s00 - lzA, s01 - lzA));
                __stcs((float2*)&lB[col0],     make_float2(s10 - lzB, s11 - lzB));
                __stcs((float2*)&lA[col0 + 8], make_float2(s20 - lzA, s21 - lzA));
                __stcs((float2*)&lB[col0 + 8], make_float2(s30 - lzB, s31 - lzB));
                __stcs((float2*)&aA[col0],     make_float2(fmaf(t00, izA, izA), fmaf(t01, izA, izA)));
                __stcs((float2*)&aB[col0],     make_float2(fmaf(t10, izB, izB), fmaf(t11, izB, izB)));
                __stcs((float2*)&aA[col0 + 8], make_float2(fmaf(t20, izA, izA), fmaf(t21, izA, izA)));
                __stcs((float2*)&aB[col0 + 8], make_float2(fmaf(t30, izB, izB), fmaf(t31, izB, izB)));
                // t fragments -> AV mma A operands
                uint32_t a0 = pack2(t00, t01);
                uint32_t a1 = pack2(t10, t11);
                uint32_t a2 = pack2(t20, t21);
                uint32_t a3 = pack2(t30, t31);
#pragma unroll
                for (int nn2 = 0; nn2 < 4; nn2++) {
                    uint32_t b0, b1, b2, b3;
                    uint32_t addr = smem_u32(&sm0[nt2 * 16 + ((lane >> 3) & 1) * 8 + (lane & 7)]
                                                  [nn2 * 16 + ((lane >> 4) << 3)]);
                    ldmat_x4_t(b0, b1, b2, b3, addr);
                    mma_bf16(acc[2 * nn2][0], acc[2 * nn2][1], acc[2 * nn2][2], acc[2 * nn2][3],
                             a0, a1, a2, a3, b0, b1);
                    mma_bf16(acc[2 * nn2 + 1][0], acc[2 * nn2 + 1][1], acc[2 * nn2 + 1][2], acc[2 * nn2 + 1][3],
                             a0, a1, a2, a3, b2, b3);
                }
            }
        }
    }

    // ---- epilogue: out = (vsum + t@v) / Z ----
    float* oA = out + rowA * 64;
    float* oB = oA + 8 * 64;
#pragma unroll
    for (int nt = 0; nt < 8; nt++) {
        float vs0 = g_vsum[b * 64 + nt * 8 + c2];
        float vs1 = g_vsum[b * 64 + nt * 8 + c2 + 1];
        *(float2*)&oA[nt * 8 + c2] = make_float2((vs0 + acc[nt][0]) * izA,
                                                 (vs1 + acc[nt][1]) * izA);
        *(float2*)&oB[nt * 8 + c2] = make_float2((vs0 + acc[nt][2]) * izB,
                                                 (vs1 + acc[nt][3]) * izB);
    }
}

// ---------------- launcher ----------------
extern "C" void kernel_launch(void* const* d_in, const int* in_sizes, int n_in,
                              void* d_out, int out_size) {
    const float* q = (const float*)d_in[0];
    const float* k = (const float*)d_in[1];
    const float* v = (const float*)d_in[2];

    float* out   = (float*)d_out;                 // [B,L,64]
    float* attn  = out + (long)BL * 64;           // [B,L,L]
    float* lattn = attn + (long)BL * L;           // [B,L,L]

    k_zero<<<2, 256>>>();
    k_prep_qk<<<2 * BL / 8, 256>>>(q, k);
    k_prep_v<<<BL / 64, 256>>>(v);

    dim3 g(L / 128, B);                           // (16,8) = 128 CTAs
    k_main<<<g, 256>>>(attn, lattn, out);
}